// round 7
// baseline (speedup 1.0000x reference)
#include <cuda_runtime.h>
#include <cstdint>

// CategoryAdder: out[b,s,:] = inputs[b,s,:] + emb
//   emb = table[categories[b,s]]  if categories[b,s] != 0 AND s != mask_positions[b]
// B=64, S=2048, D=512. categories/mask_positions int32 on device.
//
// R7: input stream staged via cp.async.bulk (1D bulk copy) into SMEM behind an
// mbarrier. Bytes-in-flight no longer bounded by registers: 8 CTAs/SM x 16KB
// outstanding. Compute reads smem, gathers L2-resident table, streams out.

static constexpr int D4 = 128;                                   // float4 per row
static constexpr long long NVEC = (long long)64 * 2048 * D4;     // 16,777,216
static constexpr int THREADS = 256;
static constexpr int CHUNK_VEC = 1024;                           // float4 per block (16KB)
static constexpr int VPT = CHUNK_VEC / THREADS;                  // 4
static constexpr unsigned NBLK = (unsigned)(NVEC / CHUNK_VEC);   // 16384

__device__ __forceinline__ uint32_t smem_u32(const void* p) {
    uint32_t a;
    asm("{ .reg .u64 t; cvta.to.shared.u64 t, %1; cvt.u32.u64 %0, t; }" : "=r"(a) : "l"(p));
    return a;
}

__global__ __launch_bounds__(THREADS)
void category_adder_kernel(const float4* __restrict__ in,
                           const int* __restrict__ cat,
                           const int* __restrict__ mask_pos,
                           const float4* __restrict__ table,
                           float4* __restrict__ out)
{
    __shared__ alignas(128) float4 sbuf[CHUNK_VEC];   // 16 KB
    __shared__ alignas(8) uint64_t mbar;

    const int tid = threadIdx.x;
    const long long chunk_base = (long long)blockIdx.x * CHUNK_VEC;

    // --- Stage input chunk via bulk async copy ---
    const uint32_t mbar_a = smem_u32(&mbar);
    if (tid == 0) {
        asm volatile("mbarrier.init.shared.b64 [%0], %1;" :: "r"(mbar_a), "r"(1) : "memory");
    }
    __syncthreads();
    if (tid == 0) {
        const uint32_t bytes = CHUNK_VEC * (uint32_t)sizeof(float4);   // 16384
        asm volatile("mbarrier.arrive.expect_tx.shared.b64 _, [%0], %1;"
                     :: "r"(mbar_a), "r"(bytes) : "memory");
        asm volatile("cp.async.bulk.shared::cta.global.mbarrier::complete_tx::bytes "
                     "[%0], [%1], %2, [%3];"
                     :: "r"(smem_u32(sbuf)), "l"(in + chunk_base), "r"(bytes), "r"(mbar_a)
                     : "memory");
    }

    // --- Overlap: compute per-element predicates + table addresses while TMA flies ---
    long long gidx[VPT];
    long long trow[VPT];
    bool add[VPT];
    int j[VPT];
    #pragma unroll
    for (int k = 0; k < VPT; k++) {
        j[k] = tid + k * THREADS;
        gidx[k] = chunk_base + j[k];
        long long row = gidx[k] >> 7;         // / D4
        int col = (int)(gidx[k] & 127);
        int b = (int)(row >> 11);             // / S
        int s = (int)(row & 2047);            // % S
        int c  = __ldg(&cat[row]);
        int mp = __ldg(&mask_pos[b]);
        add[k] = (c != 0) && (s != mp);
        trow[k] = (long long)c * D4 + col;
    }

    // Front-batch table gathers (L2-resident) before waiting on the barrier
    float4 e[VPT];
    #pragma unroll
    for (int k = 0; k < VPT; k++)
        e[k] = __ldg(&table[trow[k]]);

    // --- Wait for the staged input ---
    {
        uint32_t done;
        asm volatile(
            "{\n\t.reg .pred p;\n\t"
            "mbarrier.try_wait.parity.acquire.cta.shared::cta.b64 p, [%1], %2;\n\t"
            "selp.b32 %0, 1, 0, p;\n\t}"
            : "=r"(done) : "r"(mbar_a), "r"(0) : "memory");
        if (!done) {
            asm volatile(
                "{\n\t.reg .pred P1;\n\t"
                "WL_%=:\n\t"
                "mbarrier.try_wait.parity.acquire.cta.shared::cta.b64 P1, [%0], %1, 0x989680;\n\t"
                "@P1 bra.uni WD_%=;\n\t"
                "bra.uni WL_%=;\n\t"
                "WD_%=:\n\t}"
                :: "r"(mbar_a), "r"(0) : "memory");
        }
    }

    // --- Add + streaming store ---
    #pragma unroll
    for (int k = 0; k < VPT; k++) {
        float4 v = sbuf[j[k]];
        if (add[k]) {
            v.x += e[k].x; v.y += e[k].y; v.z += e[k].z; v.w += e[k].w;
        }
        __stcs(&out[gidx[k]], v);
    }
}

extern "C" void kernel_launch(void* const* d_in, const int* in_sizes, int n_in,
                              void* d_out, int out_size)
{
    const float4* inputs  = (const float4*)d_in[0];
    const int*    cats    = (const int*)d_in[1];
    const int*    maskpos = (const int*)d_in[2];
    const float4* table   = (const float4*)d_in[3];
    float4*       out     = (float4*)d_out;

    category_adder_kernel<<<NBLK, THREADS>>>(inputs, cats, maskpos, table, out);
}